// round 14
// baseline (speedup 1.0000x reference)
#include <cuda_runtime.h>
#include <cstdint>

#define BB 4
#define CC 32
#define TT 1024
#define UU 32
#define HH 128
#define KF 128      // feature inner dim = UU * 4 powers (p=1..4, degree-5 poly)

#define PTT 8       // prep t-tile (grid = 4*128 = 512 blocks)
#define ITILE 8     // softmax/v i-rows per block
#define TPB 16      // ffn tokens per block
#define EPAD 1028   // padded e_s row stride (floats)

// ---- scratch (device globals; no allocation allowed) ----
__device__ __align__(16) float g_G [BB*TT*KF];   // q-features (tf32-rounded)
__device__ __align__(16) float g_H [BB*TT*KF];   // k-features (tf32-rounded)
__device__ __align__(16) float g_cb[BB*TT];      // column bias (p=0 term)
__device__ __align__(16) float g_e [BB*TT*TT];   // p = exp(e + cb)
__device__ __align__(16) float g_psum[BB*TT*8];  // per-tile row partial sums
__device__ __align__(16) float g_z [BB*TT*CC];   // x + v (pre-LN1), [b][t][c]

// degree-5 tanh poly (Chebyshev-economized, |s|<=0.65, err <= 4e-5)
#define C1p ( 0.999577f)
#define C3p (-0.3252984f)
#define C5p ( 0.0952319f)

__device__ __forceinline__ float to_tf32(float x){
    float y; asm("cvt.rna.tf32.f32 %0, %1;" : "=f"(y) : "f"(x)); return y;
}
__device__ __forceinline__ float wsum(float v){
    #pragma unroll
    for (int o = 16; o; o >>= 1) v += __shfl_xor_sync(0xffffffffu, v, o);
    return v;
}
__device__ __forceinline__ void mma_tf32(float c[4], uint32_t a0, uint32_t a1,
                                         uint32_t a2, uint32_t a3,
                                         uint32_t b0, uint32_t b1){
    asm volatile(
        "mma.sync.aligned.m16n8k8.row.col.f32.tf32.tf32.f32 "
        "{%0,%1,%2,%3}, {%4,%5,%6,%7}, {%8,%9}, {%0,%1,%2,%3};"
        : "+f"(c[0]), "+f"(c[1]), "+f"(c[2]), "+f"(c[3])
        : "r"(a0), "r"(a1), "r"(a2), "r"(a3), "r"(b0), "r"(b1));
}
__device__ __forceinline__ void cp_async16(uint32_t smem, const void* g){
    asm volatile("cp.async.ca.shared.global [%0], [%1], 16;" :: "r"(smem), "l"(g));
}
__device__ __forceinline__ uint32_t s2u(const void* p){
    return (uint32_t)__cvta_generic_to_shared(p);
}

// ============================================================
// Kernel 1: projections -> features (KF=128) + column bias
// ============================================================
__global__ __launch_bounds__(256) void prep_kernel(
    const float* __restrict__ x, const float* __restrict__ Wt,
    const float* __restrict__ Wx, const float* __restrict__ bh,
    const float* __restrict__ Wa)
{
    __shared__ float xs[CC][PTT+1];
    __shared__ float Wts[CC][UU];
    __shared__ float Wxs[CC][UU];
    int b = blockIdx.x, t0 = blockIdx.y * PTT, tid = threadIdx.x;

    for (int i = tid; i < CC*UU; i += 256){ Wts[i/UU][i%UU] = Wt[i]; Wxs[i/UU][i%UU] = Wx[i]; }
    if (tid < CC*PTT){
        int c = tid / PTT, tl = tid % PTT;
        xs[c][tl] = x[(b*CC + c)*TT + t0 + tl];
    }
    __syncthreads();

    int u = tid & 31, tw = tid >> 5;
    float bhv = bh[u];
    float wa  = Wa[u];
    {
        int tl = tw;
        float q = 0.f, k = bhv;
        #pragma unroll
        for (int c = 0; c < CC; c++){
            float xv = xs[c][tl];
            q = fmaf(xv, Wts[c][u], q);
            k = fmaf(xv, Wxs[c][u], k);
        }
        int t = t0 + tl;

        float q2 = q*q, q3 = q2*q, q4 = q2*q2;
        float k2 = k*k, k3 = k2*k, k4 = k2*k2;

        float h0 = C1p*k + C3p*k3 + C5p*k4*k;
        float h1 = C1p + 3.f*C3p*k2 + 5.f*C5p*k4;
        float h2 = 3.f*C3p*k + 10.f*C5p*k3;
        float h3 = C3p + 10.f*C5p*k2;
        float h4 = 5.f*C5p*k;

        size_t base = ((size_t)(b*TT + t) << 7) + (u << 2);
        *(float4*)&g_G[base] = make_float4(to_tf32(q), to_tf32(q2), to_tf32(q3), to_tf32(q4));
        *(float4*)&g_H[base] = make_float4(to_tf32(wa*h1), to_tf32(wa*h2),
                                           to_tf32(wa*h3), to_tf32(wa*h4));

        float cb = wsum(wa * h0);
        if (u == 0) g_cb[b*TT + t] = cb;
    }
}

// ============================================================
// Kernel 2: p = exp(G @ H^T + cb), + per-tile row sums -> g_psum
// ============================================================
#define KP2 20
#define NCH (KF/16)
#define ES  132

__global__ __launch_bounds__(256) void mma_kernel()
{
    __shared__ __align__(16) union {
        struct { float G[2][128][KP2]; float H[2][128][KP2]; } k;  // 41 KB
        float es[64*ES];                                           // 33.8 KB
    } sm;
    __shared__ __align__(16) float cbs[128];

    int b  = blockIdx.x;
    int i0 = blockIdx.y * 128;
    int j0 = blockIdx.z * 128;
    int tid  = threadIdx.x;
    int lane = tid & 31;
    int wid  = tid >> 5;
    int wm = (wid >> 2) * 64;
    int wn = (wid & 3) * 32;
    int gr = lane >> 2;
    int tg = lane & 3;

    if (tid < 32) ((float4*)cbs)[tid] = ((const float4*)&g_cb[b*TT + j0])[tid];

    float acc[4][4][4];
    #pragma unroll
    for (int ms = 0; ms < 4; ms++)
        #pragma unroll
        for (int ns = 0; ns < 4; ns++)
            #pragma unroll
            for (int r = 0; r < 4; r++) acc[ms][ns][r] = 0.f;

    const float4* G4 = (const float4*)g_G;
    const float4* H4 = (const float4*)g_H;

    int row0 = tid >> 2,           c40 = tid & 3;
    int row1 = (tid + 256) >> 2,   c41 = (tid + 256) & 3;

    #define STAGE(chunk, buf) do {                                              \
        int ko = (chunk) * 4;                                                   \
        cp_async16(s2u(&sm.k.G[buf][row0][c40*4]),                              \
                   &G4[((size_t)(b*TT + i0 + row0) << 5) + ko + c40]);          \
        cp_async16(s2u(&sm.k.H[buf][row0][c40*4]),                              \
                   &H4[((size_t)(b*TT + j0 + row0) << 5) + ko + c40]);          \
        cp_async16(s2u(&sm.k.G[buf][row1][c41*4]),                              \
                   &G4[((size_t)(b*TT + i0 + row1) << 5) + ko + c41]);          \
        cp_async16(s2u(&sm.k.H[buf][row1][c41*4]),                              \
                   &H4[((size_t)(b*TT + j0 + row1) << 5) + ko + c41]);          \
        asm volatile("cp.async.commit_group;");                                 \
    } while(0)

    STAGE(0, 0);

    for (int c = 0; c < NCH; c++){
        int buf = c & 1;
        asm volatile("cp.async.wait_group 0;");
        __syncthreads();
        if (c + 1 < NCH) STAGE(c + 1, (c + 1) & 1);

        #pragma unroll
        for (int kk = 0; kk < 16; kk += 8){
            uint32_t af[4][4], bf[4][2];
            #pragma unroll
            for (int ms = 0; ms < 4; ms++){
                int r = wm + ms*16 + gr;
                af[ms][0] = __float_as_uint(sm.k.G[buf][r    ][kk + tg    ]);
                af[ms][1] = __float_as_uint(sm.k.G[buf][r + 8][kk + tg    ]);
                af[ms][2] = __float_as_uint(sm.k.G[buf][r    ][kk + tg + 4]);
                af[ms][3] = __float_as_uint(sm.k.G[buf][r + 8][kk + tg + 4]);
            }
            #pragma unroll
            for (int ns = 0; ns < 4; ns++){
                int r = wn + ns*8 + gr;
                bf[ns][0] = __float_as_uint(sm.k.H[buf][r][kk + tg    ]);
                bf[ns][1] = __float_as_uint(sm.k.H[buf][r][kk + tg + 4]);
            }
            #pragma unroll
            for (int ms = 0; ms < 4; ms++)
                #pragma unroll
                for (int ns = 0; ns < 4; ns++)
                    mma_tf32(acc[ms][ns], af[ms][0], af[ms][1], af[ms][2], af[ms][3],
                             bf[ns][0], bf[ns][1]);
        }
        __syncthreads();
    }
    #undef STAGE

    // epilogue: stage 64 rows -> exp(+cb) -> coalesced p writes + row sums
    #pragma unroll
    for (int p = 0; p < 2; p++){
        if (p) __syncthreads();
        if (wm == p*64){
            #pragma unroll
            for (int ms = 0; ms < 4; ms++){
                #pragma unroll
                for (int ns = 0; ns < 4; ns++){
                    int lr  = ms*16 + gr;
                    int col = wn + ns*8 + 2*tg;
                    *(float2*)&sm.es[lr*ES + col] =
                        make_float2(acc[ms][ns][0], acc[ms][ns][1]);
                    *(float2*)&sm.es[(lr+8)*ES + col] =
                        make_float2(acc[ms][ns][2], acc[ms][ns][3]);
                }
            }
        }
        __syncthreads();
        #pragma unroll
        for (int kq = 0; kq < 8; kq++){
            int idx = tid + kq*256;
            int row = idx >> 5, c4 = idx & 31;     // warp = one row
            float4 v  = *(float4*)&sm.es[row*ES + c4*4];
            float4 cv = *(float4*)&cbs[c4*4];
            v.x = __expf(v.x + cv.x); v.y = __expf(v.y + cv.y);
            v.z = __expf(v.z + cv.z); v.w = __expf(v.w + cv.w);
            *(float4*)&g_e[((size_t)(b*TT + i0 + p*64 + row))*TT + j0 + c4*4] = v;
            float ls = wsum((v.x + v.y) + (v.z + v.w));
            if (lane == 0)
                g_psum[((size_t)(b*TT + i0 + p*64 + row))*8 + blockIdx.z] = ls;
        }
    }
}

// ============================================================
// Kernel 3: scale+write a (inv from g_psum) + MMA v + residual
// ============================================================
__global__ __launch_bounds__(256) void softmax_v_kernel(
    const float* __restrict__ x, float* __restrict__ a_out)
{
    __shared__ __align__(16) float e_s[ITILE*EPAD];      // ~32.9 KB (holds p)
    __shared__ __align__(16) union {
        float xB[CC][68];
        float vp[8][8][33];
    } un;

    int b   = blockIdx.x;
    int i0  = blockIdx.y * ITILE;
    int tid = threadIdx.x;
    int lane = tid & 31;
    int w    = tid >> 5;
    int gr = lane >> 2, tg = lane & 3;

    #pragma unroll
    for (int l = 0; l < 8; l++)
        ((float4*)&e_s[l*EPAD])[tid] =
            ((const float4*)&g_e[(size_t)(b*TT + i0 + l)*TT])[tid];

    // inv from precomputed partial sums (warp w owns row i0+w)
    float ps = (lane < 8) ? g_psum[(size_t)(b*TT + i0 + w)*8 + lane] : 0.f;
    float inv = 1.f / (wsum(ps) + 1e-5f);   // reference: e / (sum + EPS_ATTN)
    __syncthreads();

    {   // scale + write a
        float4* er = (float4*)&e_s[w*EPAD];
        float4* ar = (float4*)&a_out[(size_t)(b*TT + i0 + w)*TT];
        #pragma unroll
        for (int it = 0; it < 8; it++){
            float4 v = er[it*32 + lane];
            v.x *= inv; v.y *= inv; v.z *= inv; v.w *= inv;
            ar[it*32 + lane] = v;
        }
    }

    float acc[4][4];
    #pragma unroll
    for (int ns = 0; ns < 4; ns++)
        #pragma unroll
        for (int r = 0; r < 4; r++) acc[ns][r] = 0.f;

    const float4* x4 = (const float4*)x;
    int xrow0 = tid >> 4,         xc0 = tid & 15;
    int xrow1 = (tid+256) >> 4,   xc1 = (tid+256) & 15;
    float4 xa0 = x4[((b*CC + xrow0) << 8) + xc0];
    float4 xa1 = x4[((b*CC + xrow1) << 8) + xc1];

    int k0 = w*8;
    for (int jt = 0; jt < 16; jt++){
        __syncthreads();
        *(float4*)&un.xB[xrow0][xc0*4] = xa0;
        *(float4*)&un.xB[xrow1][xc1*4] = xa1;
        if (jt + 1 < 16){
            xa0 = x4[((b*CC + xrow0) << 8) + ((jt+1) << 4) + xc0];
            xa1 = x4[((b*CC + xrow1) << 8) + ((jt+1) << 4) + xc1];
        }
        __syncthreads();

        uint32_t a0 = __float_as_uint(e_s[gr*EPAD + jt*64 + k0 + tg    ]);
        uint32_t a2 = __float_as_uint(e_s[gr*EPAD + jt*64 + k0 + tg + 4]);
        #pragma unroll
        for (int ns = 0; ns < 4; ns++){
            uint32_t b0 = __float_as_uint(un.xB[ns*8 + gr][k0 + tg    ]);
            uint32_t b1 = __float_as_uint(un.xB[ns*8 + gr][k0 + tg + 4]);
            mma_tf32(acc[ns], a0, 0u, a2, 0u, b0, b1);
        }
    }

    __syncthreads();
    #pragma unroll
    for (int ns = 0; ns < 4; ns++){
        un.vp[w][gr][ns*8 + 2*tg    ] = acc[ns][0];
        un.vp[w][gr][ns*8 + 2*tg + 1] = acc[ns][1];
    }
    __syncthreads();

    {
        float v = 0.f;
        #pragma unroll
        for (int ww = 0; ww < 8; ww++) v += un.vp[ww][w][lane];
        v *= inv;                       // warp w's own row's inv
        int t = i0 + w;
        float xv = x[(b*CC + lane)*TT + t];
        g_z[(b*TT + t)*CC + lane] = xv + v;
    }
}

// ============================================================
// Kernel 4: LN1 -> FFN -> residual -> LN2, all-LDS.128 datapath
//   thread owns h = 4l..4l+3  (FF1 W1 float4, FF2 h1/W2 float4)
// ============================================================
__global__ __launch_bounds__(512) void ffn_kernel(
    const float* __restrict__ gamma1, const float* __restrict__ beta1,
    const float* __restrict__ W1, const float* __restrict__ b1,
    const float* __restrict__ W2, const float* __restrict__ b2,
    const float* __restrict__ gamma2, const float* __restrict__ beta2,
    float* __restrict__ y2_out)
{
    __shared__ float W1t[CC][HH];      // 16 KB; W1t[c][h], rows 32 quads
    __shared__ float W2s[CC][HH+4];    // 16.5 KB; rows 33 quads (conflict-free LDS.128)
    __shared__ float ys [16][CC];
    __shared__ float h1s[16][HH];
    __shared__ float y2s[CC][TPB+1];

    int b = blockIdx.x, t0 = blockIdx.y * TPB, tid = threadIdx.x;
    int l = tid & 31, w = tid >> 5;

    {
        const float4* W1v = (const float4*)W1;
        const float4* W2v = (const float4*)W2;
        #pragma unroll
        for (int i = tid; i < HH*CC/4; i += 512){
            float4 v = W1v[i];
            int f = 4*i, h = f >> 5, c = f & 31;
            W1t[c][h] = v.x; W1t[c+1][h] = v.y; W1t[c+2][h] = v.z; W1t[c+3][h] = v.w;
        }
        #pragma unroll
        for (int i = tid; i < CC*HH/4; i += 512){
            float4 v = W2v[i];
            int f = 4*i, c = f >> 7, h4 = (f & 127) >> 2;
            *(float4*)&W2s[c][h4*4] = v;
        }
    }
    float4 b1r = *(const float4*)&b1[4*l];
    float b2r = b2[l];
    float g1r = gamma1[l], be1r = beta1[l], g2r = gamma2[l], be2r = beta2[l];
    __syncthreads();

    int t = t0 + w;
    float z = g_z[(b*TT + t)*CC + l];

    // LN1
    float mean = wsum(z) * (1.f/32.f);
    float d = z - mean;
    float var = wsum(d*d) * (1.f/32.f) + 1e-14f;
    float y = d * rsqrtf(var) * g1r + be1r;
    ys[w][l] = y;
    __syncwarp();

    // FF1: thread computes h = 4l..4l+3; W1 read as float4 (lane l -> quad l)
    float4 a = b1r;
    #pragma unroll
    for (int c = 0; c < CC; c++){
        float yc = ys[w][c];
        float4 wv = *(float4*)&W1t[c][4*l];
        a.x = fmaf(yc, wv.x, a.x); a.y = fmaf(yc, wv.y, a.y);
        a.z = fmaf(yc, wv.z, a.z); a.w = fmaf(yc, wv.w, a.w);
    }
    a.x = fmaxf(a.x, 0.f); a.y = fmaxf(a.y, 0.f);
    a.z = fmaxf(a.z, 0.f); a.w = fmaxf(a.w, 0.f);
    *(float4*)&h1s[w][4*l] = a;
    __syncwarp();

    // FF2: float4 streams (h1s broadcast, W2s conflict-free), 4 indep chains
    float h20 = b2r, h21 = 0.f, h22 = 0.f, h23 = 0.f;
    #pragma unroll
    for (int h4 = 0; h4 < 32; h4++){
        float4 hv = *(float4*)&h1s[w][h4*4];
        float4 wv = *(float4*)&W2s[l][h4*4];
        h20 = fmaf(hv.x, wv.x, h20);
        h21 = fmaf(hv.y, wv.y, h21);
        h22 = fmaf(hv.z, wv.z, h22);
        h23 = fmaf(hv.w, wv.w, h23);
    }
    float h2 = (h20 + h21) + (h22 + h23);

    // residual + LN2
    float z2 = y + h2;
    float m2 = wsum(z2) * (1.f/32.f);
    float d2 = z2 - m2;
    float v2 = wsum(d2*d2) * (1.f/32.f) + 1e-14f;
    float y2 = d2 * rsqrtf(v2) * g2r + be2r;

    y2s[l][w] = y2;
    __syncthreads();
    for (int i = tid; i < CC*TPB; i += 512){
        int c = i >> 4, tl = i & 15;
        y2_out[(b*CC + c)*TT + t0 + tl] = y2s[c][tl];
    }
}

// ============================================================
extern "C" void kernel_launch(void* const* d_in, const int* in_sizes, int n_in,
                              void* d_out, int out_size)
{
    const float* x      = (const float*)d_in[0];
    const float* Wt     = (const float*)d_in[1];
    const float* Wx     = (const float*)d_in[2];
    const float* bh     = (const float*)d_in[3];
    const float* Wa     = (const float*)d_in[4];
    // d_in[5] = ba: constant shift of e, cancels exactly in softmax
    const float* gamma1 = (const float*)d_in[6];
    const float* beta1  = (const float*)d_in[7];
    const float* W1     = (const float*)d_in[8];
    const float* b1     = (const float*)d_in[9];
    const float* W2     = (const float*)d_in[10];
    const float* b2     = (const float*)d_in[11];
    const float* gamma2 = (const float*)d_in[12];
    const float* beta2  = (const float*)d_in[13];

    float* out    = (float*)d_out;
    float* y2_out = out;                  // (B,C,T) = 131072 floats
    float* a_out  = out + BB*CC*TT;       // (B,T,T) = 4194304 floats

    prep_kernel     <<<dim3(BB, TT/PTT),   256>>>(x, Wt, Wx, bh, Wa);
    mma_kernel      <<<dim3(BB, TT/128, TT/128), 256>>>();
    softmax_v_kernel<<<dim3(BB, TT/ITILE), 256>>>(x, a_out);
    ffn_kernel      <<<dim3(BB, TT/TPB),   512>>>(gamma1, beta1, W1, b1, W2, b2,
                                                  gamma2, beta2, y2_out);
}

// round 15
// speedup vs baseline: 1.0455x; 1.0455x over previous
#include <cuda_runtime.h>
#include <cstdint>

#define BB 4
#define CC 32
#define TT 1024
#define UU 32
#define HH 128
#define KF 128      // feature inner dim = UU * 4 powers (p=1..4, degree-5 poly)

#define PTT 8       // prep t-tile (grid = 4*128 = 512 blocks)
#define ITILE 8     // softmax/v i-rows per block
#define TPB 16      // ffn tokens per block (8 warps x 2 tokens)
#define EPAD 1028   // padded e_s row stride (floats)

// ---- scratch (device globals; no allocation allowed) ----
__device__ __align__(16) float g_G [BB*TT*KF];   // q-features (tf32-rounded)
__device__ __align__(16) float g_H [BB*TT*KF];   // k-features (tf32-rounded)
__device__ __align__(16) float g_cb[BB*TT];      // column bias (p=0 term)
__device__ __align__(16) float g_psum[BB*TT*8];  // per-tile row partial sums
__device__ __align__(16) float g_z [BB*TT*CC];   // x + v (pre-LN1), [b][t][c]

// degree-5 tanh poly (Chebyshev-economized, |s|<=0.65, err <= 4e-5)
#define C1p ( 0.999577f)
#define C3p (-0.3252984f)
#define C5p ( 0.0952319f)

__device__ __forceinline__ float to_tf32(float x){
    float y; asm("cvt.rna.tf32.f32 %0, %1;" : "=f"(y) : "f"(x)); return y;
}
__device__ __forceinline__ float wsum(float v){
    #pragma unroll
    for (int o = 16; o; o >>= 1) v += __shfl_xor_sync(0xffffffffu, v, o);
    return v;
}
__device__ __forceinline__ void wsum2(float& a, float& b){
    #pragma unroll
    for (int o = 16; o; o >>= 1){
        a += __shfl_xor_sync(0xffffffffu, a, o);
        b += __shfl_xor_sync(0xffffffffu, b, o);
    }
}
__device__ __forceinline__ void mma_tf32(float c[4], uint32_t a0, uint32_t a1,
                                         uint32_t a2, uint32_t a3,
                                         uint32_t b0, uint32_t b1){
    asm volatile(
        "mma.sync.aligned.m16n8k8.row.col.f32.tf32.tf32.f32 "
        "{%0,%1,%2,%3}, {%4,%5,%6,%7}, {%8,%9}, {%0,%1,%2,%3};"
        : "+f"(c[0]), "+f"(c[1]), "+f"(c[2]), "+f"(c[3])
        : "r"(a0), "r"(a1), "r"(a2), "r"(a3), "r"(b0), "r"(b1));
}
__device__ __forceinline__ void cp_async16(uint32_t smem, const void* g){
    asm volatile("cp.async.ca.shared.global [%0], [%1], 16;" :: "r"(smem), "l"(g));
}
__device__ __forceinline__ uint32_t s2u(const void* p){
    return (uint32_t)__cvta_generic_to_shared(p);
}

// ============================================================
// Kernel 1: projections -> features (KF=128) + column bias
// ============================================================
__global__ __launch_bounds__(256) void prep_kernel(
    const float* __restrict__ x, const float* __restrict__ Wt,
    const float* __restrict__ Wx, const float* __restrict__ bh,
    const float* __restrict__ Wa)
{
    __shared__ float xs[CC][PTT+1];
    __shared__ float Wts[CC][UU];
    __shared__ float Wxs[CC][UU];
    int b = blockIdx.x, t0 = blockIdx.y * PTT, tid = threadIdx.x;

    for (int i = tid; i < CC*UU; i += 256){ Wts[i/UU][i%UU] = Wt[i]; Wxs[i/UU][i%UU] = Wx[i]; }
    if (tid < CC*PTT){
        int c = tid / PTT, tl = tid % PTT;
        xs[c][tl] = x[(b*CC + c)*TT + t0 + tl];
    }
    __syncthreads();

    int u = tid & 31, tw = tid >> 5;
    float bhv = bh[u];
    float wa  = Wa[u];
    {
        int tl = tw;
        float q = 0.f, k = bhv;
        #pragma unroll
        for (int c = 0; c < CC; c++){
            float xv = xs[c][tl];
            q = fmaf(xv, Wts[c][u], q);
            k = fmaf(xv, Wxs[c][u], k);
        }
        int t = t0 + tl;

        float q2 = q*q, q3 = q2*q, q4 = q2*q2;
        float k2 = k*k, k3 = k2*k, k4 = k2*k2;

        float h0 = C1p*k + C3p*k3 + C5p*k4*k;
        float h1 = C1p + 3.f*C3p*k2 + 5.f*C5p*k4;
        float h2 = 3.f*C3p*k + 10.f*C5p*k3;
        float h3 = C3p + 10.f*C5p*k2;
        float h4 = 5.f*C5p*k;

        size_t base = ((size_t)(b*TT + t) << 7) + (u << 2);
        *(float4*)&g_G[base] = make_float4(to_tf32(q), to_tf32(q2), to_tf32(q3), to_tf32(q4));
        *(float4*)&g_H[base] = make_float4(to_tf32(wa*h1), to_tf32(wa*h2),
                                           to_tf32(wa*h3), to_tf32(wa*h4));

        float cb = wsum(wa * h0);
        if (u == 0) g_cb[b*TT + t] = cb;
    }
}

// ============================================================
// Kernel 2: p = exp(G @ H^T + cb) -> a_out (unscaled), row sums -> g_psum
// ============================================================
#define KP2 20
#define NCH (KF/16)
#define ES  132

__global__ __launch_bounds__(256) void mma_kernel(float* __restrict__ p_out)
{
    __shared__ __align__(16) union {
        struct { float G[2][128][KP2]; float H[2][128][KP2]; } k;  // 41 KB
        float es[64*ES];                                           // 33.8 KB
    } sm;
    __shared__ __align__(16) float cbs[128];

    int b  = blockIdx.x;
    int i0 = blockIdx.y * 128;
    int j0 = blockIdx.z * 128;
    int tid  = threadIdx.x;
    int lane = tid & 31;
    int wid  = tid >> 5;
    int wm = (wid >> 2) * 64;
    int wn = (wid & 3) * 32;
    int gr = lane >> 2;
    int tg = lane & 3;

    if (tid < 32) ((float4*)cbs)[tid] = ((const float4*)&g_cb[b*TT + j0])[tid];

    float acc[4][4][4];
    #pragma unroll
    for (int ms = 0; ms < 4; ms++)
        #pragma unroll
        for (int ns = 0; ns < 4; ns++)
            #pragma unroll
            for (int r = 0; r < 4; r++) acc[ms][ns][r] = 0.f;

    const float4* G4 = (const float4*)g_G;
    const float4* H4 = (const float4*)g_H;

    int row0 = tid >> 2,           c40 = tid & 3;
    int row1 = (tid + 256) >> 2,   c41 = (tid + 256) & 3;

    #define STAGE(chunk, buf) do {                                              \
        int ko = (chunk) * 4;                                                   \
        cp_async16(s2u(&sm.k.G[buf][row0][c40*4]),                              \
                   &G4[((size_t)(b*TT + i0 + row0) << 5) + ko + c40]);          \
        cp_async16(s2u(&sm.k.H[buf][row0][c40*4]),                              \
                   &H4[((size_t)(b*TT + j0 + row0) << 5) + ko + c40]);          \
        cp_async16(s2u(&sm.k.G[buf][row1][c41*4]),                              \
                   &G4[((size_t)(b*TT + i0 + row1) << 5) + ko + c41]);          \
        cp_async16(s2u(&sm.k.H[buf][row1][c41*4]),                              \
                   &H4[((size_t)(b*TT + j0 + row1) << 5) + ko + c41]);          \
        asm volatile("cp.async.commit_group;");                                 \
    } while(0)

    STAGE(0, 0);

    for (int c = 0; c < NCH; c++){
        int buf = c & 1;
        asm volatile("cp.async.wait_group 0;");
        __syncthreads();
        if (c + 1 < NCH) STAGE(c + 1, (c + 1) & 1);

        #pragma unroll
        for (int kk = 0; kk < 16; kk += 8){
            uint32_t af[4][4], bf[4][2];
            #pragma unroll
            for (int ms = 0; ms < 4; ms++){
                int r = wm + ms*16 + gr;
                af[ms][0] = __float_as_uint(sm.k.G[buf][r    ][kk + tg    ]);
                af[ms][1] = __float_as_uint(sm.k.G[buf][r + 8][kk + tg    ]);
                af[ms][2] = __float_as_uint(sm.k.G[buf][r    ][kk + tg + 4]);
                af[ms][3] = __float_as_uint(sm.k.G[buf][r + 8][kk + tg + 4]);
            }
            #pragma unroll
            for (int ns = 0; ns < 4; ns++){
                int r = wn + ns*8 + gr;
                bf[ns][0] = __float_as_uint(sm.k.H[buf][r][kk + tg    ]);
                bf[ns][1] = __float_as_uint(sm.k.H[buf][r][kk + tg + 4]);
            }
            #pragma unroll
            for (int ms = 0; ms < 4; ms++)
                #pragma unroll
                for (int ns = 0; ns < 4; ns++)
                    mma_tf32(acc[ms][ns], af[ms][0], af[ms][1], af[ms][2], af[ms][3],
                             bf[ns][0], bf[ns][1]);
        }
        __syncthreads();
    }
    #undef STAGE

    // epilogue: stage 64 rows -> exp(+cb) -> coalesced p writes + row sums
    #pragma unroll
    for (int p = 0; p < 2; p++){
        if (p) __syncthreads();
        if (wm == p*64){
            #pragma unroll
            for (int ms = 0; ms < 4; ms++){
                #pragma unroll
                for (int ns = 0; ns < 4; ns++){
                    int lr  = ms*16 + gr;
                    int col = wn + ns*8 + 2*tg;
                    *(float2*)&sm.es[lr*ES + col] =
                        make_float2(acc[ms][ns][0], acc[ms][ns][1]);
                    *(float2*)&sm.es[(lr+8)*ES + col] =
                        make_float2(acc[ms][ns][2], acc[ms][ns][3]);
                }
            }
        }
        __syncthreads();
        #pragma unroll
        for (int kq = 0; kq < 8; kq++){
            int idx = tid + kq*256;
            int row = idx >> 5, c4 = idx & 31;     // warp = one row
            float4 v  = *(float4*)&sm.es[row*ES + c4*4];
            float4 cv = *(float4*)&cbs[c4*4];
            v.x = __expf(v.x + cv.x); v.y = __expf(v.y + cv.y);
            v.z = __expf(v.z + cv.z); v.w = __expf(v.w + cv.w);
            *(float4*)&p_out[((size_t)(b*TT + i0 + p*64 + row))*TT + j0 + c4*4] = v;
            float ls = wsum((v.x + v.y) + (v.z + v.w));
            if (lane == 0)
                g_psum[((size_t)(b*TT + i0 + p*64 + row))*8 + blockIdx.z] = ls;
        }
    }
}

// ============================================================
// Kernel 3: in-place scale of a (inv from g_psum) + MMA v + residual
// ============================================================
__global__ __launch_bounds__(256) void softmax_v_kernel(
    const float* __restrict__ x, float* __restrict__ a_out)
{
    __shared__ __align__(16) float e_s[ITILE*EPAD];      // ~32.9 KB (holds p)
    __shared__ __align__(16) union {
        float xB[CC][68];
        float vp[8][8][33];
    } un;

    int b   = blockIdx.x;
    int i0  = blockIdx.y * ITILE;
    int tid = threadIdx.x;
    int lane = tid & 31;
    int w    = tid >> 5;
    int gr = lane >> 2, tg = lane & 3;

    #pragma unroll
    for (int l = 0; l < 8; l++)
        ((float4*)&e_s[l*EPAD])[tid] =
            ((const float4*)&a_out[(size_t)(b*TT + i0 + l)*TT])[tid];

    float ps = (lane < 8) ? g_psum[(size_t)(b*TT + i0 + w)*8 + lane] : 0.f;
    float inv = 1.f / (wsum(ps) + 1e-5f);   // reference: e / (sum + EPS_ATTN)
    __syncthreads();

    {   // scale + write a (in place)
        float4* er = (float4*)&e_s[w*EPAD];
        float4* ar = (float4*)&a_out[(size_t)(b*TT + i0 + w)*TT];
        #pragma unroll
        for (int it = 0; it < 8; it++){
            float4 v = er[it*32 + lane];
            v.x *= inv; v.y *= inv; v.z *= inv; v.w *= inv;
            ar[it*32 + lane] = v;
        }
    }

    float acc[4][4];
    #pragma unroll
    for (int ns = 0; ns < 4; ns++)
        #pragma unroll
        for (int r = 0; r < 4; r++) acc[ns][r] = 0.f;

    const float4* x4 = (const float4*)x;
    int xrow0 = tid >> 4,         xc0 = tid & 15;
    int xrow1 = (tid+256) >> 4,   xc1 = (tid+256) & 15;
    float4 xa0 = x4[((b*CC + xrow0) << 8) + xc0];
    float4 xa1 = x4[((b*CC + xrow1) << 8) + xc1];

    int k0 = w*8;
    for (int jt = 0; jt < 16; jt++){
        __syncthreads();
        *(float4*)&un.xB[xrow0][xc0*4] = xa0;
        *(float4*)&un.xB[xrow1][xc1*4] = xa1;
        if (jt + 1 < 16){
            xa0 = x4[((b*CC + xrow0) << 8) + ((jt+1) << 4) + xc0];
            xa1 = x4[((b*CC + xrow1) << 8) + ((jt+1) << 4) + xc1];
        }
        __syncthreads();

        uint32_t a0 = __float_as_uint(e_s[gr*EPAD + jt*64 + k0 + tg    ]);
        uint32_t a2 = __float_as_uint(e_s[gr*EPAD + jt*64 + k0 + tg + 4]);
        #pragma unroll
        for (int ns = 0; ns < 4; ns++){
            uint32_t b0 = __float_as_uint(un.xB[ns*8 + gr][k0 + tg    ]);
            uint32_t b1 = __float_as_uint(un.xB[ns*8 + gr][k0 + tg + 4]);
            mma_tf32(acc[ns], a0, 0u, a2, 0u, b0, b1);
        }
    }

    __syncthreads();
    #pragma unroll
    for (int ns = 0; ns < 4; ns++){
        un.vp[w][gr][ns*8 + 2*tg    ] = acc[ns][0];
        un.vp[w][gr][ns*8 + 2*tg + 1] = acc[ns][1];
    }
    __syncthreads();

    {
        float v = 0.f;
        #pragma unroll
        for (int ww = 0; ww < 8; ww++) v += un.vp[ww][w][lane];
        v *= inv;
        int t = i0 + w;
        float xv = x[(b*CC + lane)*TT + t];
        g_z[(b*TT + t)*CC + lane] = xv + v;
    }
}

// ============================================================
// Kernel 4: LN1 -> FFN -> residual -> LN2; 2 tokens/warp (ILP x2),
//   smem FF2 (no shuffles), weight reads shared across both tokens
// ============================================================
__global__ __launch_bounds__(256) void ffn_kernel(
    const float* __restrict__ gamma1, const float* __restrict__ beta1,
    const float* __restrict__ W1, const float* __restrict__ b1,
    const float* __restrict__ W2, const float* __restrict__ b2,
    const float* __restrict__ gamma2, const float* __restrict__ beta2,
    float* __restrict__ y2_out)
{
    __shared__ float W1t[CC][HH];      // 16 KB; W1t[c][h]
    __shared__ float W2s[CC][HH+4];    // 16.5 KB; 33-quad rows, conflict-free LDS.128
    __shared__ float ys [TPB][CC];     // 2 KB
    __shared__ float h1s[TPB][HH];     // 8 KB
    __shared__ float y2s[CC][TPB+1];   // 2.2 KB   (total ~44.7 KB)

    int b = blockIdx.x, t0 = blockIdx.y * TPB, tid = threadIdx.x;
    int l = tid & 31, w = tid >> 5;   // w: 0..7; tokens ta=w, tb=w+8

    {
        const float4* W1v = (const float4*)W1;
        const float4* W2v = (const float4*)W2;
        #pragma unroll
        for (int i = tid; i < HH*CC/4; i += 256){
            float4 v = W1v[i];
            int f = 4*i, h = f >> 5, c = f & 31;
            W1t[c][h] = v.x; W1t[c+1][h] = v.y; W1t[c+2][h] = v.z; W1t[c+3][h] = v.w;
        }
        #pragma unroll
        for (int i = tid; i < CC*HH/4; i += 256){
            float4 v = W2v[i];
            int f = 4*i, c = f >> 7, h4 = (f & 127) >> 2;
            *(float4*)&W2s[c][h4*4] = v;
        }
    }
    float4 b1r = *(const float4*)&b1[4*l];
    float b2r = b2[l];
    float g1r = gamma1[l], be1r = beta1[l], g2r = gamma2[l], be2r = beta2[l];
    __syncthreads();

    int ta = w, tb = w + 8;
    float za = g_z[(b*TT + t0 + ta)*CC + l];
    float zb = g_z[(b*TT + t0 + tb)*CC + l];

    // LN1 dual-interleaved
    float sa = za, sb = zb;
    wsum2(sa, sb);
    float da = za - sa*(1.f/32.f), db = zb - sb*(1.f/32.f);
    float qa = da*da, qb = db*db;
    wsum2(qa, qb);
    float ya = da * rsqrtf(qa*(1.f/32.f) + 1e-14f) * g1r + be1r;
    float yb = db * rsqrtf(qb*(1.f/32.f) + 1e-14f) * g1r + be1r;
    ys[ta][l] = ya; ys[tb][l] = yb;
    __syncwarp();

    // FF1: thread computes h=4l..4l+3 for both tokens; weight read shared
    float4 aa = b1r, ab = b1r;
    #pragma unroll
    for (int c = 0; c < CC; c++){
        float4 wv = *(float4*)&W1t[c][4*l];
        float yca = ys[ta][c], ycb = ys[tb][c];
        aa.x = fmaf(yca, wv.x, aa.x); ab.x = fmaf(ycb, wv.x, ab.x);
        aa.y = fmaf(yca, wv.y, aa.y); ab.y = fmaf(ycb, wv.y, ab.y);
        aa.z = fmaf(yca, wv.z, aa.z); ab.z = fmaf(ycb, wv.z, ab.z);
        aa.w = fmaf(yca, wv.w, aa.w); ab.w = fmaf(ycb, wv.w, ab.w);
    }
    aa.x = fmaxf(aa.x, 0.f); aa.y = fmaxf(aa.y, 0.f);
    aa.z = fmaxf(aa.z, 0.f); aa.w = fmaxf(aa.w, 0.f);
    ab.x = fmaxf(ab.x, 0.f); ab.y = fmaxf(ab.y, 0.f);
    ab.z = fmaxf(ab.z, 0.f); ab.w = fmaxf(ab.w, 0.f);
    *(float4*)&h1s[ta][4*l] = aa;
    *(float4*)&h1s[tb][4*l] = ab;
    __syncwarp();

    // FF2: 8 independent chains (4 per token); weight read shared
    float a0 = b2r, a1 = 0.f, a2 = 0.f, a3 = 0.f;
    float c0 = b2r, c1 = 0.f, c2 = 0.f, c3 = 0.f;
    #pragma unroll
    for (int h4 = 0; h4 < 32; h4++){
        float4 wv  = *(float4*)&W2s[l][h4*4];
        float4 hva = *(float4*)&h1s[ta][h4*4];
        float4 hvb = *(float4*)&h1s[tb][h4*4];
        a0 = fmaf(hva.x, wv.x, a0); c0 = fmaf(hvb.x, wv.x, c0);
        a1 = fmaf(hva.y, wv.y, a1); c1 = fmaf(hvb.y, wv.y, c1);
        a2 = fmaf(hva.z, wv.z, a2); c2 = fmaf(hvb.z, wv.z, c2);
        a3 = fmaf(hva.w, wv.w, a3); c3 = fmaf(hvb.w, wv.w, c3);
    }
    float h2a = (a0 + a1) + (a2 + a3);
    float h2b = (c0 + c1) + (c2 + c3);

    // residual + LN2 dual-interleaved
    float z2a = ya + h2a, z2b = yb + h2b;
    float ma = z2a, mb = z2b;
    wsum2(ma, mb);
    float d2a = z2a - ma*(1.f/32.f), d2b = z2b - mb*(1.f/32.f);
    float v2a = d2a*d2a, v2b = d2b*d2b;
    wsum2(v2a, v2b);
    float y2a = d2a * rsqrtf(v2a*(1.f/32.f) + 1e-14f) * g2r + be2r;
    float y2b = d2b * rsqrtf(v2b*(1.f/32.f) + 1e-14f) * g2r + be2r;

    y2s[l][ta] = y2a; y2s[l][tb] = y2b;
    __syncthreads();
    for (int i = tid; i < CC*TPB; i += 256){
        int c = i >> 4, tl = i & 15;
        y2_out[(b*CC + c)*TT + t0 + tl] = y2s[c][tl];
    }
}

// ============================================================
extern "C" void kernel_launch(void* const* d_in, const int* in_sizes, int n_in,
                              void* d_out, int out_size)
{
    const float* x      = (const float*)d_in[0];
    const float* Wt     = (const float*)d_in[1];
    const float* Wx     = (const float*)d_in[2];
    const float* bh     = (const float*)d_in[3];
    const float* Wa     = (const float*)d_in[4];
    // d_in[5] = ba: constant shift of e, cancels exactly in softmax
    const float* gamma1 = (const float*)d_in[6];
    const float* beta1  = (const float*)d_in[7];
    const float* W1     = (const float*)d_in[8];
    const float* b1     = (const float*)d_in[9];
    const float* W2     = (const float*)d_in[10];
    const float* b2     = (const float*)d_in[11];
    const float* gamma2 = (const float*)d_in[12];
    const float* beta2  = (const float*)d_in[13];

    float* out    = (float*)d_out;
    float* y2_out = out;                  // (B,C,T) = 131072 floats
    float* a_out  = out + BB*CC*TT;       // (B,T,T) = 4194304 floats

    prep_kernel     <<<dim3(BB, TT/PTT),   256>>>(x, Wt, Wx, bh, Wa);
    mma_kernel      <<<dim3(BB, TT/128, TT/128), 256>>>(a_out);
    softmax_v_kernel<<<dim3(BB, TT/ITILE), 256>>>(x, a_out);
    ffn_kernel      <<<dim3(BB, TT/TPB),   256>>>(gamma1, beta1, W1, b1, W2, b2,
                                                  gamma2, beta2, y2_out);
}